// round 1
// baseline (speedup 1.0000x reference)
#include <cuda_runtime.h>
#include <math.h>

// Problem constants (fixed shapes from setup_inputs)
#define D 64
#define R 64
#define T 4096
#define B 8
#define NTOK (B * T)                  // 32768
#define STRENGTH 0.1f
#define SC 0.17677669529663687f       // sqrt(2/64)

#define K1_BLOCKS 128                 // 8 batches * 16 chunks
#define CHUNKS_PER_BATCH 16

// Scratch (device globals — no allocation)
__device__ float g_phi[(size_t)NTOK * R];        // 8 MB
__device__ float g_partial[K1_BLOCKS * R];
__device__ float g_phisum[B * R];
__device__ float g_grav[NTOK];                   // includes STRENGTH factor

// ---------------------------------------------------------------------------
// K1: per-token mass + phi; phi -> scratch; block partial of sum(mass*phi)
// One warp handles 32 tokens, 4 at a time (weights reused 4x per LDS).
// ---------------------------------------------------------------------------
__global__ __launch_bounds__(256) void k1_phi_mass(
    const float* __restrict__ coords, const float* __restrict__ w1,
    const float* __restrict__ b1, const float* __restrict__ w2,
    const float* __restrict__ b2, const float* __restrict__ W,
    const float* __restrict__ bR)
{
    __shared__ float s_w1[64 * 68];   // row-major [r][k], stride 68 (conflict-free f4)
    __shared__ float s_Wt[64 * 68];   // W transposed: [r][k]
    __shared__ float s_b1[64], s_w2[64], s_bR[64];
    __shared__ float s_red[8 * 64];

    const int tid = threadIdx.x;

    for (int idx = tid; idx < 4096; idx += 256) {
        int r = idx >> 6, k = idx & 63;
        s_w1[r * 68 + k] = w1[idx];              // w1 is [r][k] row-major
    }
    for (int idx = tid; idx < 4096; idx += 256) {
        int k = idx >> 6, r = idx & 63;
        s_Wt[r * 68 + k] = W[idx];               // W is [k][r] row-major
    }
    if (tid < 64) { s_b1[tid] = b1[tid]; s_w2[tid] = w2[tid]; s_bR[tid] = bR[tid]; }
    __syncthreads();

    const int lane = tid & 31, warp = tid >> 5;
    const int bb = blockIdx.x >> 4, chunk = blockIdx.x & 15;
    const int tokBase = bb * T + chunk * 256 + warp * 32;
    const float b2v = b2[0];

    const float4* w1a = (const float4*)(s_w1 + lane * 68);
    const float4* w1b = (const float4*)(s_w1 + (lane + 32) * 68);
    const float4* Wta = (const float4*)(s_Wt + lane * 68);
    const float4* Wtb = (const float4*)(s_Wt + (lane + 32) * 68);

    float accA = 0.f, accB = 0.f;

    for (int g = 0; g < 8; ++g) {
        const int t0 = tokBase + g * 4;
        const float4* c4 = (const float4*)(coords + (size_t)t0 * D);
        float h0[4] = {0.f,0.f,0.f,0.f}, h1[4] = {0.f,0.f,0.f,0.f};
        float p0[4] = {0.f,0.f,0.f,0.f}, p1[4] = {0.f,0.f,0.f,0.f};

        #pragma unroll
        for (int k4 = 0; k4 < 16; ++k4) {
            float4 wa = w1a[k4], wb = w1b[k4], va = Wta[k4], vb = Wtb[k4];
            #pragma unroll
            for (int j = 0; j < 4; ++j) {
                float4 c = c4[j * 16 + k4];   // token t0+j, coords[4k4..4k4+3] (uniform)
                h0[j] = fmaf(c.x, wa.x, h0[j]); h0[j] = fmaf(c.y, wa.y, h0[j]);
                h0[j] = fmaf(c.z, wa.z, h0[j]); h0[j] = fmaf(c.w, wa.w, h0[j]);
                h1[j] = fmaf(c.x, wb.x, h1[j]); h1[j] = fmaf(c.y, wb.y, h1[j]);
                h1[j] = fmaf(c.z, wb.z, h1[j]); h1[j] = fmaf(c.w, wb.w, h1[j]);
                p0[j] = fmaf(c.x, va.x, p0[j]); p0[j] = fmaf(c.y, va.y, p0[j]);
                p0[j] = fmaf(c.z, va.z, p0[j]); p0[j] = fmaf(c.w, va.w, p0[j]);
                p1[j] = fmaf(c.x, vb.x, p1[j]); p1[j] = fmaf(c.y, vb.y, p1[j]);
                p1[j] = fmaf(c.z, vb.z, p1[j]); p1[j] = fmaf(c.w, vb.w, p1[j]);
            }
        }

        #pragma unroll
        for (int j = 0; j < 4; ++j) {
            float hh0 = fmaxf(h0[j] + s_b1[lane], 0.f);
            float hh1 = fmaxf(h1[j] + s_b1[lane + 32], 0.f);
            float mp = fmaf(hh0, s_w2[lane], hh1 * s_w2[lane + 32]);
            mp += __shfl_xor_sync(0xffffffffu, mp, 16);
            mp += __shfl_xor_sync(0xffffffffu, mp, 8);
            mp += __shfl_xor_sync(0xffffffffu, mp, 4);
            mp += __shfl_xor_sync(0xffffffffu, mp, 2);
            mp += __shfl_xor_sync(0xffffffffu, mp, 1);
            float x = mp + b2v;
            float mass = (x > 15.f) ? x : log1pf(expf(x));
            float phi0 = SC * cosf(p0[j] + s_bR[lane]);
            float phi1 = SC * cosf(p1[j] + s_bR[lane + 32]);
            g_phi[(size_t)(t0 + j) * R + lane] = phi0;
            g_phi[(size_t)(t0 + j) * R + lane + 32] = phi1;
            accA = fmaf(mass, phi0, accA);
            accB = fmaf(mass, phi1, accB);
        }
    }

    s_red[warp * 64 + lane] = accA;
    s_red[warp * 64 + lane + 32] = accB;
    __syncthreads();
    if (tid < 64) {
        float s = 0.f;
        #pragma unroll
        for (int w = 0; w < 8; ++w) s += s_red[w * 64 + tid];
        g_partial[blockIdx.x * 64 + tid] = s;
    }
}

// ---------------------------------------------------------------------------
// K2: deterministic reduce of chunk partials -> phi_sum[b][r]
// ---------------------------------------------------------------------------
__global__ void k2_reduce()
{
    const int bb = blockIdx.x;        // 8 blocks
    const int r = threadIdx.x;        // 64 threads
    float s = 0.f;
    #pragma unroll
    for (int c = 0; c < CHUNKS_PER_BATCH; ++c)
        s += g_partial[(bb * CHUNKS_PER_BATCH + c) * 64 + r];
    g_phisum[bb * 64 + r] = s;
}

// ---------------------------------------------------------------------------
// K3: grav[t] = STRENGTH * dot(phi[t], phi_sum[batch])  (warp per 4 tokens)
// ---------------------------------------------------------------------------
__global__ __launch_bounds__(256) void k3_grav()
{
    const int tid = threadIdx.x, lane = tid & 31, warp = tid >> 5;
    const int bb = blockIdx.x >> 4, chunk = blockIdx.x & 15;
    const int tokBase = bb * T + chunk * 256 + warp * 32;
    const float ps0 = g_phisum[bb * 64 + lane];
    const float ps1 = g_phisum[bb * 64 + lane + 32];

    #pragma unroll
    for (int g = 0; g < 8; ++g) {
        const int t0 = tokBase + g * 4;
        float v[4];
        #pragma unroll
        for (int j = 0; j < 4; ++j) {
            const float* ph = g_phi + (size_t)(t0 + j) * R;
            v[j] = fmaf(ph[lane], ps0, ph[lane + 32] * ps1);
        }
        #pragma unroll
        for (int s = 16; s >= 1; s >>= 1) {
            #pragma unroll
            for (int j = 0; j < 4; ++j)
                v[j] += __shfl_xor_sync(0xffffffffu, v[j], s);
        }
        if (lane == 0) {
            g_grav[t0 + 0] = STRENGTH * v[0];
            g_grav[t0 + 1] = STRENGTH * v[1];
            g_grav[t0 + 2] = STRENGTH * v[2];
            g_grav[t0 + 3] = STRENGTH * v[3];
        }
    }
}

// ---------------------------------------------------------------------------
// K4: the roofline — 1 GiB copy of G with fused diagonal add
// ---------------------------------------------------------------------------
__global__ __launch_bounds__(256) void k4_copy(const float4* __restrict__ G4,
                                               float4* __restrict__ O4)
{
    const unsigned idx = blockIdx.x * 256u + threadIdx.x;   // < 2^25
    float4 v = G4[idx];
    const unsigned tok = idx >> 10;            // 1024 float4 per 64x64 tile
    const unsigned within = idx & 1023u;
    const int i  = (int)(within >> 4);         // row (16 float4 per row)
    const int j0 = (int)((within & 15u) << 2); // first col of this float4
    const int d  = i - j0;
    if ((unsigned)d < 4u) {
        const float gv = g_grav[tok];
        if      (d == 0) v.x += gv;
        else if (d == 1) v.y += gv;
        else if (d == 2) v.z += gv;
        else             v.w += gv;
    }
    O4[idx] = v;
}

// ---------------------------------------------------------------------------
extern "C" void kernel_launch(void* const* d_in, const int* in_sizes, int n_in,
                              void* d_out, int out_size)
{
    const float* G      = (const float*)d_in[0];
    const float* coords = (const float*)d_in[1];
    const float* w1     = (const float*)d_in[2];
    const float* b1     = (const float*)d_in[3];
    const float* w2     = (const float*)d_in[4];
    const float* b2     = (const float*)d_in[5];
    const float* W      = (const float*)d_in[6];
    const float* bR     = (const float*)d_in[7];
    float* out = (float*)d_out;

    k1_phi_mass<<<K1_BLOCKS, 256>>>(coords, w1, b1, w2, b2, W, bR);
    k2_reduce<<<B, 64>>>();
    k3_grav<<<K1_BLOCKS, 256>>>();

    const unsigned total4 = (unsigned)((size_t)NTOK * D * D / 4);   // 33554432
    k4_copy<<<total4 / 256, 256>>>((const float4*)G, (float4*)out);
}